// round 8
// baseline (speedup 1.0000x reference)
#include <cuda_runtime.h>

#define N_TOK 8192
#define DDIM  256
#define HDIM  64
#define NEXP  32
#define TM    16        // tokens per ffn tile
#define FFN_CTAS 544    // >= max tiles: 8192/16=512 full + <=31 partial tails

typedef unsigned long long u64;

// packed-f32x2 helpers (sm_100+; ptxas never emits FFMA2 from C++)
#define DUP2(d, s)    asm("mov.b64 %0, {%1, %1};" : "=l"(d) : "f"(s))
#define FMA2(c, a, b) asm("fma.rn.f32x2 %0, %1, %2, %0;" : "+l"(c) : "l"(a), "l"(b))
#define UNPK(lo, hi, p) asm("mov.b64 {%0, %1}, %2;" : "=f"(lo), "=f"(hi) : "l"(p))

// ---------------- scratch (no allocations allowed) ----------------
__device__ int g_cursor[NEXP];            // zero-init; k_prep resets each call
__device__ int g_cnt[NEXP];
__device__ int g_perm[NEXP * N_TOK];      // fixed 8192-slot bucket per expert (1MB)
__device__ int g_tile_e[FFN_CTAS];
__device__ int g_tile_t[FFN_CTAS];

// ---------------- kernel 1: router GEMM + argmax + fused scatter ----------------
// 128 CTAs x 128 thr; CTA tile 64 tok x 32 exp, K=256 pipelined. Epilogue:
// bias + first-max argmax (strict >, lower-idx ties) + block-aggregated
// scatter into per-expert buckets (1 cursor atomic per expert per CTA).
__global__ void __launch_bounds__(128) k_router(const float* __restrict__ x,
                                                const float* __restrict__ rw,
                                                const float* __restrict__ rb) {
    const int tid = threadIdx.x;
    const int tx  = tid & 7;       // expert group: experts tx*4..tx*4+3
    const int ty  = tid >> 3;      // token group: tokens ty*4..ty*4+3
    const int tok0 = blockIdx.x * 64;

    __shared__ float Xs[32][68];
    __shared__ float Ws[32][32];
    __shared__ int   tokE[64];
    __shared__ int   hist[NEXP], sbase[NEXP], scur[NEXP];

    if (tid < NEXP) { hist[tid] = 0; scur[tid] = 0; }

    const float4* Xg = (const float4*)x;
    const float4* Wg = (const float4*)rw;

    float4 xv[4], wv[2];
#pragma unroll
    for (int i = 0; i < 4; i++) {
        int lin = tid + i * 128;
        xv[i] = Xg[(size_t)(tok0 + (lin & 63)) * 64 + (lin >> 6)];
    }
#pragma unroll
    for (int i = 0; i < 2; i++) {
        int lin = tid + i * 128;
        wv[i] = Wg[(size_t)(lin & 31) * 64 + (lin >> 5)];
    }

    float acc[4][4];
#pragma unroll
    for (int i = 0; i < 4; i++)
#pragma unroll
        for (int j = 0; j < 4; j++) acc[i][j] = 0.f;

    for (int c = 0; c < 8; c++) {
#pragma unroll
        for (int i = 0; i < 4; i++) {
            int lin = tid + i * 128;
            int tok = lin & 63, kq = lin >> 6;
            Xs[kq * 4 + 0][tok] = xv[i].x;
            Xs[kq * 4 + 1][tok] = xv[i].y;
            Xs[kq * 4 + 2][tok] = xv[i].z;
            Xs[kq * 4 + 3][tok] = xv[i].w;
        }
#pragma unroll
        for (int i = 0; i < 2; i++) {
            int lin = tid + i * 128;
            int ee = lin & 31, kq = lin >> 5;
            Ws[kq * 4 + 0][ee] = wv[i].x;
            Ws[kq * 4 + 1][ee] = wv[i].y;
            Ws[kq * 4 + 2][ee] = wv[i].z;
            Ws[kq * 4 + 3][ee] = wv[i].w;
        }
        __syncthreads();
        if (c < 7) {
            int kq0 = (c + 1) * 8;
#pragma unroll
            for (int i = 0; i < 4; i++) {
                int lin = tid + i * 128;
                xv[i] = Xg[(size_t)(tok0 + (lin & 63)) * 64 + kq0 + (lin >> 6)];
            }
#pragma unroll
            for (int i = 0; i < 2; i++) {
                int lin = tid + i * 128;
                wv[i] = Wg[(size_t)(lin & 31) * 64 + kq0 + (lin >> 5)];
            }
        }
#pragma unroll
        for (int k = 0; k < 32; k++) {
            float4 a = *(const float4*)&Xs[k][ty * 4];
            float4 b = *(const float4*)&Ws[k][tx * 4];
            float av[4] = {a.x, a.y, a.z, a.w};
            float bv[4] = {b.x, b.y, b.z, b.w};
#pragma unroll
            for (int i = 0; i < 4; i++)
#pragma unroll
                for (int j = 0; j < 4; j++) acc[i][j] += av[i] * bv[j];
        }
        __syncthreads();
    }

    // bias + argmax (+ smem histogram)
    float4 rbv4 = *(const float4*)&rb[tx * 4];
    float rbv[4] = {rbv4.x, rbv4.y, rbv4.z, rbv4.w};
#pragma unroll
    for (int i = 0; i < 4; i++) {
        float v = acc[i][0] + rbv[0];
        int idx = tx * 4;
#pragma unroll
        for (int j = 1; j < 4; j++) {
            float val = acc[i][j] + rbv[j];
            if (val > v) { v = val; idx = tx * 4 + j; }   // strict > = first-max
        }
#pragma unroll
        for (int m = 1; m < 8; m <<= 1) {
            float ov = __shfl_xor_sync(0xffffffffu, v, m);
            int   oi = __shfl_xor_sync(0xffffffffu, idx, m);
            if (ov > v || (ov == v && oi < idx)) { v = ov; idx = oi; }
        }
        if (tx == 0) {
            tokE[ty * 4 + i] = idx;
            atomicAdd(&hist[idx], 1);
        }
    }
    __syncthreads();
    // fused scatter: one global atomic per (CTA, expert); then smem rank
    if (tid < NEXP) sbase[tid] = hist[tid] ? atomicAdd(&g_cursor[tid], hist[tid]) : 0;
    __syncthreads();
    if (tid < 64) {
        int e = tokE[tid];
        int r = atomicAdd(&scur[e], 1);
        g_perm[e * N_TOK + sbase[e] + r] = tok0 + tid;
    }
}

// ---------------- kernel 2: prep (1 warp) ----------------
// Reads per-expert counts, builds the FFN (expert, tile) map, resets cursors.
__global__ void k_prep() {
    int lane = threadIdx.x;
    int cnt = g_cursor[lane];
    g_cnt[lane] = cnt;
    g_cursor[lane] = 0;                    // ready for next graph replay
    int tiles = (cnt + TM - 1) / TM;
    int s = tiles;
#pragma unroll
    for (int off = 1; off < 32; off <<= 1) {
        int t = __shfl_up_sync(0xffffffffu, s, off);
        if (lane >= off) s += t;
    }
    int base = s - tiles;
    for (int i = 0; i < tiles; i++) {
        g_tile_e[base + i] = lane;
        g_tile_t[base + i] = i;
    }
    int T = __shfl_sync(0xffffffffu, s, 31);
    for (int i = T + lane; i < FFN_CTAS; i += 32) g_tile_e[i] = -1;
}

// ---------------- kernel 3: grouped expert FFN (TM=16, 4 CTAs/SM) ----------------
// ~544 CTAs x 128 thr, 16 tokens/CTA -> ~4 CTAs/SM (16 warps) for latency
// cover. Thread tile 2 tok x 4 h packed in f32x2; double-buffered smem arena
// with reg-prefetch pipeline (same scheme as before).
__global__ void __launch_bounds__(128) k_ffn(const float* __restrict__ x,
                                             const float* __restrict__ W1,
                                             const float* __restrict__ b1,
                                             const float* __restrict__ W2,
                                             const float* __restrict__ b2,
                                             float* __restrict__ out) {
    const int e = g_tile_e[blockIdx.x];
    if (e < 0) return;
    const int tile = g_tile_t[blockIdx.x];
    const int cnt  = g_cnt[e];
    const int bkt  = e * N_TOK;

    const int tid = threadIdx.x;
    const int tx  = tid & 15;        // 16 h-groups of 4
    const int ty  = tid >> 4;        // 8 token-groups of 2

    int rem = cnt - tile * TM;
    const int nt = rem > TM ? TM : rem;

    __shared__ int   toks[TM];
    __shared__ float Hs[HDIM][20];       // [h][tok], padded
    __shared__ float arena[8192];        // 32KB union
#define XS(b,k,t)  arena[(b)*640 + (k)*20 + (t)]          // 2*32*20 = 1280
#define WB1(b,k,h) arena[1280 + (b)*2048 + (k)*64 + (h)]  // +4096
#define WB2(b,k,nn) arena[(b)*4096 + (k)*64 + (nn)]       // reuse whole arena

    if (tid < TM) toks[tid] = g_perm[bkt + min(tile * TM + tid, cnt - 1)];
    __syncthreads();

    const float4* Xg  = (const float4*)x;
    const float4* Wg1 = (const float4*)(W1 + (size_t)e * DDIM * HDIM);
    const float4* W2g = (const float4*)(W2 + (size_t)e * HDIM * DDIM);

    const int tokA = tid & 15, kqA = tid >> 4;    // 16 tok x 8 kq = 128 thr

    float4 xv, wv[4];
    xv = Xg[(size_t)toks[tokA] * 64 + kqA];
#pragma unroll
    for (int i = 0; i < 4; i++) wv[i] = Wg1[tid + i * 128];

    u64 acc2[4];
#pragma unroll
    for (int j = 0; j < 4; j++) acc2[j] = 0ull;

    // ================= GEMM1: 8 chunks of K=32 =================
    for (int c = 0; c < 8; c++) {
        const int b = c & 1;
        XS(b, kqA * 4 + 0, tokA) = xv.x;
        XS(b, kqA * 4 + 1, tokA) = xv.y;
        XS(b, kqA * 4 + 2, tokA) = xv.z;
        XS(b, kqA * 4 + 3, tokA) = xv.w;
#pragma unroll
        for (int i = 0; i < 4; i++) {
            int lin = tid + i * 128;
            *(float4*)&WB1(b, lin >> 4, (lin & 15) * 4) = wv[i];
        }
        if (c < 7) {
            int kq0 = (c + 1) * 8;
            xv = Xg[(size_t)toks[tokA] * 64 + kq0 + kqA];
#pragma unroll
            for (int i = 0; i < 4; i++) wv[i] = Wg1[(kq0 << 6) + tid + i * 128];
        }
        __syncthreads();
#pragma unroll
        for (int k = 0; k < 32; k++) {
            u64 a = *(const u64*)&XS(b, k, ty * 2);       // 2 tokens packed
            float4 bb = *(const float4*)&WB1(b, k, tx * 4);
            u64 bd0, bd1, bd2, bd3;
            DUP2(bd0, bb.x); DUP2(bd1, bb.y); DUP2(bd2, bb.z); DUP2(bd3, bb.w);
            FMA2(acc2[0], a, bd0);
            FMA2(acc2[1], a, bd1);
            FMA2(acc2[2], a, bd2);
            FMA2(acc2[3], a, bd3);
        }
    }

    // bias + relu -> Hs[h][tok]
    {
        float4 bb = *(const float4*)&b1[e * HDIM + tx * 4];
        float bv[4] = {bb.x, bb.y, bb.z, bb.w};
#pragma unroll
        for (int j = 0; j < 4; j++) {
            float lo, hi;
            UNPK(lo, hi, acc2[j]);
            lo += bv[j]; hi += bv[j];
            Hs[tx * 4 + j][ty * 2 + 0] = lo > 0.f ? lo : 0.f;
            Hs[tx * 4 + j][ty * 2 + 1] = hi > 0.f ? hi : 0.f;
        }
    }

    // ---- GEMM2 prologue: prefetch W2 chunk 0 ----
    float4 wv2[8];
#pragma unroll
    for (int i = 0; i < 8; i++) {
        int lin = tid + i * 128;
        wv2[i] = W2g[(lin >> 4) * 64 + (lin & 15)];
    }
    __syncthreads();   // GEMM1 arena reads + Hs writes complete

    // ================= GEMM2: 4 chunks of 64 output cols =================
    for (int c = 0; c < 4; c++) {
        const int b = c & 1;
#pragma unroll
        for (int i = 0; i < 8; i++) {
            int lin = tid + i * 128;
            *(float4*)&WB2(b, lin >> 4, (lin & 15) * 4) = wv2[i];
        }
        if (c < 3) {
#pragma unroll
            for (int i = 0; i < 8; i++) {
                int lin = tid + i * 128;
                wv2[i] = W2g[(lin >> 4) * 64 + (c + 1) * 16 + (lin & 15)];
            }
        }
        __syncthreads();

#pragma unroll
        for (int j = 0; j < 4; j++) acc2[j] = 0ull;

#pragma unroll 8
        for (int k = 0; k < HDIM; k++) {
            u64 a = *(const u64*)&Hs[k][ty * 2];
            float4 bb = *(const float4*)&WB2(b, k, tx * 4);
            u64 bd0, bd1, bd2, bd3;
            DUP2(bd0, bb.x); DUP2(bd1, bb.y); DUP2(bd2, bb.z); DUP2(bd3, bb.w);
            FMA2(acc2[0], a, bd0);
            FMA2(acc2[1], a, bd1);
            FMA2(acc2[2], a, bd2);
            FMA2(acc2[3], a, bd3);
        }

        // epilogue: bias + relu + store this 64-col chunk
        float4 cb = *(const float4*)&b2[e * DDIM + c * 64 + tx * 4];
        float cv[4] = {cb.x, cb.y, cb.z, cb.w};
        float r[2][4];
#pragma unroll
        for (int j = 0; j < 4; j++) {
            float lo, hi;
            UNPK(lo, hi, acc2[j]);
            r[0][j] = fmaxf(lo + cv[j], 0.f);
            r[1][j] = fmaxf(hi + cv[j], 0.f);
        }
#pragma unroll
        for (int i = 0; i < 2; i++) {
            int ti = ty * 2 + i;
            if (ti < nt) {
                size_t row = (size_t)toks[ti] * DDIM;
                float4 rv;
                rv.x = r[i][0]; rv.y = r[i][1]; rv.z = r[i][2]; rv.w = r[i][3];
                *(float4*)&out[row + c * 64 + tx * 4] = rv;
            }
        }
    }
#undef XS
#undef WB1
#undef WB2
}

// ---------------- launch ----------------
extern "C" void kernel_launch(void* const* d_in, const int* in_sizes, int n_in,
                              void* d_out, int out_size) {
    const float* x   = (const float*)d_in[0];
    const float* rw  = (const float*)d_in[1];
    const float* rb  = (const float*)d_in[2];
    const float* W1  = (const float*)d_in[3];
    const float* b1  = (const float*)d_in[4];
    const float* W2  = (const float*)d_in[5];
    const float* b2  = (const float*)d_in[6];
    float* out = (float*)d_out;

    k_router<<<N_TOK / 64, 128>>>(x, rw, rb);
    k_prep<<<1, 32>>>();
    k_ffn<<<FFN_CTAS, 128>>>(x, W1, b1, W2, b2, out);
}

// round 9
// speedup vs baseline: 1.1736x; 1.1736x over previous
#include <cuda_runtime.h>

#define N_TOK 8192
#define DDIM  256
#define HDIM  64
#define NEXP  32
#define TM    32        // tokens per ffn tile
#define FFN_CTAS 288    // >= max tiles: 8192/32=256 full + <=31 partial tails

typedef unsigned long long u64;

// packed-f32x2 helpers (sm_100+; ptxas never emits FFMA2 from C++)
#define DUP2(d, s)    asm("mov.b64 %0, {%1, %1};" : "=l"(d) : "f"(s))
#define FMA2(c, a, b) asm("fma.rn.f32x2 %0, %1, %2, %0;" : "+l"(c) : "l"(a), "l"(b))
#define UNPK(lo, hi, p) asm("mov.b64 {%0, %1}, %2;" : "=f"(lo), "=f"(hi) : "l"(p))

// ---------------- scratch (no allocations allowed) ----------------
__device__ int g_idx[N_TOK];
__device__ int g_counts[NEXP];     // zero at init; k_scan resets each call
__device__ int g_off[NEXP + 1];
__device__ int g_cursor[NEXP];
__device__ int g_perm[N_TOK];

// ---------------- kernel 1: router GEMM + fused argmax ----------------
// 256 CTAs x 128 thr. CTA tile: 32 tokens x 32 experts, K=256 (8 chunks of 32,
// reg-prefetch pipelined). Thread tile 2 tok x 4 exp in f32x2. Epilogue: bias
// + first-max argmax (strict >, lower-idx ties) + smem-aggregated histogram.
__global__ void __launch_bounds__(128) k_router(const float* __restrict__ x,
                                                const float* __restrict__ rw,
                                                const float* __restrict__ rb) {
    const int tid = threadIdx.x;
    const int tx  = tid & 7;       // expert group: experts tx*4..tx*4+3
    const int ty  = tid >> 3;      // token group: tokens ty*2, ty*2+1
    const int tok0 = blockIdx.x * 32;

    __shared__ float Xs[32][36];   // [k][tok]
    __shared__ float Ws[32][32];   // [k][exp]
    __shared__ int   hist[NEXP];

    if (tid < NEXP) hist[tid] = 0;

    const float4* Xg = (const float4*)x;
    const float4* Wg = (const float4*)rw;

    // prefetch chunk 0
    float4 xv[2], wv[2];
#pragma unroll
    for (int i = 0; i < 2; i++) {
        int lin = tid + i * 128;            // 0..255: tok=lin&31, kq=lin>>5
        xv[i] = Xg[(size_t)(tok0 + (lin & 31)) * 64 + (lin >> 5)];
        wv[i] = Wg[(size_t)(lin & 31) * 64 + (lin >> 5)];
    }

    u64 acc2[4];
#pragma unroll
    for (int j = 0; j < 4; j++) acc2[j] = 0ull;

    for (int c = 0; c < 8; c++) {
        // STS prefetched chunk (transposed)
#pragma unroll
        for (int i = 0; i < 2; i++) {
            int lin = tid + i * 128;
            int tok = lin & 31, kq = lin >> 5;
            Xs[kq * 4 + 0][tok] = xv[i].x;
            Xs[kq * 4 + 1][tok] = xv[i].y;
            Xs[kq * 4 + 2][tok] = xv[i].z;
            Xs[kq * 4 + 3][tok] = xv[i].w;
            Ws[kq * 4 + 0][tok] = wv[i].x;   // tok == expert index here
            Ws[kq * 4 + 1][tok] = wv[i].y;
            Ws[kq * 4 + 2][tok] = wv[i].z;
            Ws[kq * 4 + 3][tok] = wv[i].w;
        }
        __syncthreads();
        // prefetch chunk c+1
        if (c < 7) {
            int kq0 = (c + 1) * 8;
#pragma unroll
            for (int i = 0; i < 2; i++) {
                int lin = tid + i * 128;
                xv[i] = Xg[(size_t)(tok0 + (lin & 31)) * 64 + kq0 + (lin >> 5)];
                wv[i] = Wg[(size_t)(lin & 31) * 64 + kq0 + (lin >> 5)];
            }
        }
        // compute chunk c
#pragma unroll
        for (int k = 0; k < 32; k++) {
            u64 a = *(const u64*)&Xs[k][ty * 2];          // 2 tokens packed
            float4 b = *(const float4*)&Ws[k][tx * 4];
            u64 bd0, bd1, bd2, bd3;
            DUP2(bd0, b.x); DUP2(bd1, b.y); DUP2(bd2, b.z); DUP2(bd3, b.w);
            FMA2(acc2[0], a, bd0);
            FMA2(acc2[1], a, bd1);
            FMA2(acc2[2], a, bd2);
            FMA2(acc2[3], a, bd3);
        }
        __syncthreads();
    }

    // epilogue: bias + argmax over this thread's 4 experts x 2 tokens
    float4 rbv4 = *(const float4*)&rb[tx * 4];
    float rbv[4] = {rbv4.x, rbv4.y, rbv4.z, rbv4.w};
    float lv[2][4];
#pragma unroll
    for (int j = 0; j < 4; j++) {
        float lo, hi;
        UNPK(lo, hi, acc2[j]);
        lv[0][j] = lo + rbv[j];
        lv[1][j] = hi + rbv[j];
    }
#pragma unroll
    for (int i = 0; i < 2; i++) {
        float v = lv[i][0];
        int idx = tx * 4;
#pragma unroll
        for (int j = 1; j < 4; j++) {
            if (lv[i][j] > v) { v = lv[i][j]; idx = tx * 4 + j; }  // first-max
        }
        // reduce across the 8 expert-lanes (xor m<8 stays within token group)
#pragma unroll
        for (int m = 1; m < 8; m <<= 1) {
            float ov = __shfl_xor_sync(0xffffffffu, v, m);
            int   oi = __shfl_xor_sync(0xffffffffu, idx, m);
            if (ov > v || (ov == v && oi < idx)) { v = ov; idx = oi; }
        }
        if (tx == 0) {
            g_idx[tok0 + ty * 2 + i] = idx;
            atomicAdd(&hist[idx], 1);
        }
    }
    __syncthreads();
    if (tid < NEXP && hist[tid]) atomicAdd(&g_counts[tid], hist[tid]);
}

// ---------------- kernel 2: 32-entry exclusive scan (1 warp) ----------------
__global__ void k_scan() {
    int lane = threadIdx.x;
    int c = g_counts[lane];
    int s = c;
#pragma unroll
    for (int off = 1; off < 32; off <<= 1) {
        int t = __shfl_up_sync(0xffffffffu, s, off);
        if (lane >= off) s += t;
    }
    g_off[lane]    = s - c;
    g_cursor[lane] = s - c;
    if (lane == 31) g_off[NEXP] = s;
    g_counts[lane] = 0;                // ready for next graph replay
}

// ---------------- kernel 3: scatter (block-aggregated counting sort) ----------------
__global__ void __launch_bounds__(256) k_scatter() {
    __shared__ int hist[NEXP], sbase[NEXP], scur[NEXP];
    int tid = threadIdx.x;
    int n = blockIdx.x * 256 + tid;
    int e = g_idx[n];
    if (tid < NEXP) { hist[tid] = 0; scur[tid] = 0; }
    __syncthreads();
    atomicAdd(&hist[e], 1);
    __syncthreads();
    if (tid < NEXP) sbase[tid] = atomicAdd(&g_cursor[tid], hist[tid]);
    __syncthreads();
    int r = atomicAdd(&scur[e], 1);
    g_perm[sbase[e] + r] = n;
}

// ---------------- kernel 4: grouped expert FFN (pipelined + FFMA2) ----------------
__global__ void __launch_bounds__(128) k_ffn(const float* __restrict__ x,
                                             const float* __restrict__ W1,
                                             const float* __restrict__ b1,
                                             const float* __restrict__ W2,
                                             const float* __restrict__ b2,
                                             float* __restrict__ out) {
    // map blockIdx.x -> (expert e, tile)
    int e = -1, tile = 0;
    {
        int t = blockIdx.x, acc = 0, prev = g_off[0];
#pragma unroll
        for (int ee = 0; ee < NEXP; ee++) {
            int nxt = g_off[ee + 1];
            int tiles_e = (nxt - prev + TM - 1) >> 5;
            if (e < 0 && t < acc + tiles_e) { e = ee; tile = t - acc; }
            acc += tiles_e;
            prev = nxt;
        }
        if (e < 0) return;
    }

    const int off0 = g_off[e];
    const int cnt  = g_off[e + 1] - off0;

    const int tid = threadIdx.x;
    const int tx  = tid & 15;        // 16 h-groups of 4
    const int ty  = tid >> 4;        // 8 token-groups of 4

    int rem = cnt - tile * TM;
    const int nt = rem > TM ? TM : rem;

    __shared__ int   toks[TM];
    __shared__ float Hs[HDIM][36];       // [h][tok], padded
    __shared__ float arena[8192];        // 32KB union
#define XS(b,k,t)  arena[(b)*1152 + (k)*36 + (t)]
#define WB1(b,k,h) arena[2304 + (b)*2048 + (k)*64 + (h)]
#define WB2(b,k,nn) arena[(b)*4096 + (k)*64 + (nn)]

    if (tid < TM) toks[tid] = g_perm[off0 + min(tile * TM + tid, cnt - 1)];
    __syncthreads();

    const float4* Xg  = (const float4*)x;
    const float4* Wg1 = (const float4*)(W1 + (size_t)e * DDIM * HDIM);
    const float4* W2g = (const float4*)(W2 + (size_t)e * HDIM * DDIM);

    const int tokA = tid & 31,        kqA = tid >> 5;
    const int tokB = tokA,            kqB = kqA + 4;

    float4 xv0, xv1, wv[4];
    xv0 = Xg[(size_t)toks[tokA] * 64 + 0 + kqA];
    xv1 = Xg[(size_t)toks[tokB] * 64 + 0 + kqB];
#pragma unroll
    for (int i = 0; i < 4; i++) wv[i] = Wg1[tid + i * 128];

    u64 acc2[2][4];
#pragma unroll
    for (int p = 0; p < 2; p++)
#pragma unroll
        for (int j = 0; j < 4; j++) acc2[p][j] = 0ull;

    // ================= GEMM1: 8 chunks of K=32 =================
    for (int c = 0; c < 8; c++) {
        const int b = c & 1;
        XS(b, kqA * 4 + 0, tokA) = xv0.x;
        XS(b, kqA * 4 + 1, tokA) = xv0.y;
        XS(b, kqA * 4 + 2, tokA) = xv0.z;
        XS(b, kqA * 4 + 3, tokA) = xv0.w;
        XS(b, kqB * 4 + 0, tokB) = xv1.x;
        XS(b, kqB * 4 + 1, tokB) = xv1.y;
        XS(b, kqB * 4 + 2, tokB) = xv1.z;
        XS(b, kqB * 4 + 3, tokB) = xv1.w;
#pragma unroll
        for (int i = 0; i < 4; i++) {
            int lin = tid + i * 128;
            *(float4*)&WB1(b, lin >> 4, (lin & 15) * 4) = wv[i];
        }
        if (c < 7) {
            int k0 = (c + 1) * 32;
            xv0 = Xg[(size_t)toks[tokA] * 64 + (k0 >> 2) + kqA];
            xv1 = Xg[(size_t)toks[tokB] * 64 + (k0 >> 2) + kqB];
#pragma unroll
            for (int i = 0; i < 4; i++) wv[i] = Wg1[(k0 << 4) + tid + i * 128];
        }
        __syncthreads();
#pragma unroll
        for (int k = 0; k < 32; k++) {
            ulonglong2 a = *(const ulonglong2*)&XS(b, k, ty * 4);
            float4 bb = *(const float4*)&WB1(b, k, tx * 4);
            u64 bd0, bd1, bd2, bd3;
            DUP2(bd0, bb.x); DUP2(bd1, bb.y); DUP2(bd2, bb.z); DUP2(bd3, bb.w);
            FMA2(acc2[0][0], a.x, bd0); FMA2(acc2[1][0], a.y, bd0);
            FMA2(acc2[0][1], a.x, bd1); FMA2(acc2[1][1], a.y, bd1);
            FMA2(acc2[0][2], a.x, bd2); FMA2(acc2[1][2], a.y, bd2);
            FMA2(acc2[0][3], a.x, bd3); FMA2(acc2[1][3], a.y, bd3);
        }
    }

    // bias + relu -> Hs[h][tok]
    {
        float4 bb = *(const float4*)&b1[e * HDIM + tx * 4];
        float bv[4] = {bb.x, bb.y, bb.z, bb.w};
#pragma unroll
        for (int p = 0; p < 2; p++) {
#pragma unroll
            for (int j = 0; j < 4; j++) {
                float lo, hi;
                UNPK(lo, hi, acc2[p][j]);
                lo += bv[j]; hi += bv[j];
                Hs[tx * 4 + j][ty * 4 + 2 * p]     = lo > 0.f ? lo : 0.f;
                Hs[tx * 4 + j][ty * 4 + 2 * p + 1] = hi > 0.f ? hi : 0.f;
            }
        }
    }

    float4 wv2[8];
#pragma unroll
    for (int i = 0; i < 8; i++) {
        int lin = tid + i * 128;
        wv2[i] = W2g[(lin >> 4) * 64 + (lin & 15)];
    }
    __syncthreads();

    // ================= GEMM2: 4 chunks of 64 output cols =================
    for (int c = 0; c < 4; c++) {
        const int b = c & 1;
#pragma unroll
        for (int i = 0; i < 8; i++) {
            int lin = tid + i * 128;
            *(float4*)&WB2(b, lin >> 4, (lin & 15) * 4) = wv2[i];
        }
        if (c < 3) {
#pragma unroll
            for (int i = 0; i < 8; i++) {
                int lin = tid + i * 128;
                wv2[i] = W2g[(lin >> 4) * 64 + (c + 1) * 16 + (lin & 15)];
            }
        }
        __syncthreads();

#pragma unroll
        for (int p = 0; p < 2; p++)
#pragma unroll
            for (int j = 0; j < 4; j++) acc2[p][j] = 0ull;

#pragma unroll 8
        for (int k = 0; k < HDIM; k++) {
            ulonglong2 a = *(const ulonglong2*)&Hs[k][ty * 4];
            float4 bb = *(const float4*)&WB2(b, k, tx * 4);
            u64 bd0, bd1, bd2, bd3;
            DUP2(bd0, bb.x); DUP2(bd1, bb.y); DUP2(bd2, bb.z); DUP2(bd3, bb.w);
            FMA2(acc2[0][0], a.x, bd0); FMA2(acc2[1][0], a.y, bd0);
            FMA2(acc2[0][1], a.x, bd1); FMA2(acc2[1][1], a.y, bd1);
            FMA2(acc2[0][2], a.x, bd2); FMA2(acc2[1][2], a.y, bd2);
            FMA2(acc2[0][3], a.x, bd3); FMA2(acc2[1][3], a.y, bd3);
        }

        float4 cb = *(const float4*)&b2[e * DDIM + c * 64 + tx * 4];
        float cv[4] = {cb.x, cb.y, cb.z, cb.w};
        float r[4][4];
#pragma unroll
        for (int p = 0; p < 2; p++) {
#pragma unroll
            for (int j = 0; j < 4; j++) {
                float lo, hi;
                UNPK(lo, hi, acc2[p][j]);
                r[2 * p][j]     = fmaxf(lo + cv[j], 0.f);
                r[2 * p + 1][j] = fmaxf(hi + cv[j], 0.f);
            }
        }
#pragma unroll
        for (int i = 0; i < 4; i++) {
            int ti = ty * 4 + i;
            if (ti < nt) {
                size_t row = (size_t)toks[ti] * DDIM;
                float4 rv;
                rv.x = r[i][0]; rv.y = r[i][1]; rv.z = r[i][2]; rv.w = r[i][3];
                *(float4*)&out[row + c * 64 + tx * 4] = rv;
            }
        }
    }
#undef XS
#undef WB1
#undef WB2
}

// ---------------- launch ----------------
extern "C" void kernel_launch(void* const* d_in, const int* in_sizes, int n_in,
                              void* d_out, int out_size) {
    const float* x   = (const float*)d_in[0];
    const float* rw  = (const float*)d_in[1];
    const float* rb  = (const float*)d_in[2];
    const float* W1  = (const float*)d_in[3];
    const float* b1  = (const float*)d_in[4];
    const float* W2  = (const float*)d_in[5];
    const float* b2  = (const float*)d_in[6];
    float* out = (float*)d_out;

    k_router<<<N_TOK / 32, 128>>>(x, rw, rb);
    k_scan<<<1, 32>>>();
    k_scatter<<<N_TOK / 256, 256>>>();
    k_ffn<<<FFN_CTAS, 128>>>(x, W1, b1, W2, b2, out);
}